// round 14
// baseline (speedup 1.0000x reference)
#include <cuda_runtime.h>
#include <cuda_fp16.h>
#include <cstdint>

// Problem constants
#define B_     128
#define T_     26
#define IN_    512
#define H_     512
#define NC_    38
#define STEPS_ 26
#define BPE_   50257
#define WP_    30522
#define ROWS_  (B_ * STEPS_)   // 3328
#define GRID_SCAN 128

// ---------------- device scratch ----------------
__device__ float g_Hproj[ROWS_ * H_];                  // i2h(batch_H) fp32
__device__ float g_ph[B_ * H_];                        // h @ h2h^T + b
__device__ float g_gates[B_ * 4 * H_];                 // h-part of gates (perm rows)
__device__ __align__(16) __half g_xh[B_ * 1024];       // [ctx | h] fp16 per batch
__device__ __align__(16) __half g_WA[2560 * 512];      // [Whh_perm | h2h] fp16
__device__ __align__(16) __half g_Wih_h[2048 * 512];   // Wih(:,:512) perm rows fp16
__device__ float g_Wt[NC_ * 4 * H_];                   // onehot col + bih + bhh (orig layout)
__device__ __align__(16) __half g_Hs_h[ROWS_ * H_];    // hidden states fp16
__device__ __align__(16) __half g_char_h[NC_ * H_];
__device__ __align__(16) __half g_bpe_h[(size_t)BPE_ * H_];
__device__ __align__(16) __half g_wp_h[(size_t)WP_ * H_];
__device__ __align__(16) __half g_i2h_h[H_ * IN_];     // i2h fp16
__device__ __align__(16) __half g_bh_h[ROWS_ * IN_];   // batch_H fp16
__device__ float g_zeros[512];                         // zero-init, never written

// distributed-flag grid barrier state (monotonic, replay-safe)
__device__ volatile int g_flags[GRID_SCAN];   // arrival counter per CTA (b>0)
__device__ volatile int g_relgen;             // release counter (written by CTA 0)

// ======================= helpers =================
__device__ __forceinline__ uint32_t smem_u32(const void* p) {
    return (uint32_t)__cvta_generic_to_shared(p);
}
__device__ __forceinline__ void cp_async16(uint32_t dst, const void* src, int src_bytes) {
    asm volatile("cp.async.cg.shared.global [%0], [%1], 16, %2;"
                 :: "r"(dst), "l"(src), "r"(src_bytes));
}
#define CP_COMMIT() asm volatile("cp.async.commit_group;" ::: "memory")
#define CP_WAIT0()  asm volatile("cp.async.wait_group 0;" ::: "memory")
#define CP_WAIT1()  asm volatile("cp.async.wait_group 1;" ::: "memory")
#define CP_WAIT2()  asm volatile("cp.async.wait_group 2;" ::: "memory")

__device__ __forceinline__ void ldsm_x4(uint32_t* r, uint32_t addr) {
    asm volatile("ldmatrix.sync.aligned.m8n8.x4.shared.b16 {%0,%1,%2,%3}, [%4];"
                 : "=r"(r[0]), "=r"(r[1]), "=r"(r[2]), "=r"(r[3]) : "r"(addr));
}
__device__ __forceinline__ void mma16816(float* d, const uint32_t* a, const uint32_t* b) {
    asm volatile(
        "mma.sync.aligned.m16n8k16.row.col.f32.f16.f16.f32 "
        "{%0,%1,%2,%3}, {%4,%5,%6,%7}, {%8,%9}, {%0,%1,%2,%3};"
        : "+f"(d[0]), "+f"(d[1]), "+f"(d[2]), "+f"(d[3])
        : "r"(a[0]), "r"(a[1]), "r"(a[2]), "r"(a[3]), "r"(b[0]), "r"(b[1]));
}

// Distributed-flag grid barrier. myc = target count (monotonic, pre-incremented
// by caller). CTA b>0: publish own flag, spin on release. CTA 0: threads poll
// one flag each in parallel, then thread 0 publishes release. No atomics, no
// same-address RMW serialization. Fence/acquire structure mirrors the proven
// counter barrier.
__device__ __forceinline__ void grid_bar(int b, int myc) {
    __syncthreads();
    if (b == 0) {
        if (threadIdx.x == 0) __threadfence();     // publish CTA 0's writes
        __syncthreads();
        if (threadIdx.x > 0 && threadIdx.x < GRID_SCAN) {
            while (g_flags[threadIdx.x] < myc) {}
        }
        __syncthreads();                            // all arrivals observed
        if (threadIdx.x == 0) {
            __threadfence();                        // acquire + order release
            g_relgen = myc;                         // release
        }
    } else {
        if (threadIdx.x == 0) {
            __threadfence();                        // publish this CTA's writes
            g_flags[b] = myc;                       // arrive
            while (g_relgen < myc) {}               // wait for release
            __threadfence();                        // acquire
        }
    }
    __syncthreads();
}

// ====== GEMM core macro: A[128,K]h (lda), W rows n0w..n0w+32 (ldw) =========
// 4-stage cp.async, issue-3-ahead, single sync per iteration.
#define PH_GEMM_CORE(Aptr, lda, K, Wptr, ldw, n0w, sA, sB)                     \
    float acc[2][2][4];                                                        \
    _Pragma("unroll")                                                          \
    for (int i = 0; i < 2; i++)                                                \
        _Pragma("unroll")                                                      \
        for (int j = 0; j < 2; j++)                                            \
            _Pragma("unroll")                                                  \
            for (int q = 0; q < 4; q++) acc[i][j][q] = 0.f;                    \
    {                                                                          \
        const int NIT = (K) >> 6;                                              \
        const int tid_ = threadIdx.x;                                          \
        const int wid_ = tid_ >> 5, lane_ = tid_ & 31;                         \
        const int wm_ = wid_ & 3, wn_ = wid_ >> 2;                             \
        auto issue = [&](int kt) {                                             \
            int st = kt & 3;                                                   \
            int k0 = kt << 6;                                                  \
            __half* pa = (sA) + st * (128 * 72);                               \
            __half* pb = (sB) + st * (32 * 72);                                \
            _Pragma("unroll")                                                  \
            for (int c = 0; c < 4; c++) {                                      \
                int idx = tid_ + 256 * c;                                      \
                int row = idx >> 3, q = (idx & 7) * 8;                         \
                cp_async16(smem_u32(pa + row * 72 + q),                        \
                           (Aptr) + (size_t)row * (lda) + k0 + q, 16);         \
            }                                                                  \
            { int row = tid_ >> 3, q = (tid_ & 7) * 8;                         \
              cp_async16(smem_u32(pb + row * 72 + q),                          \
                         (Wptr) + (size_t)((n0w) + row) * (ldw) + k0 + q, 16); } \
            CP_COMMIT();                                                       \
        };                                                                     \
        issue(0); issue(1); issue(2);                                          \
        for (int kt = 0; kt < NIT; kt++) {                                     \
            if (kt < NIT - 2)      { CP_WAIT2(); }                             \
            else if (kt == NIT - 2){ CP_WAIT1(); }                             \
            else                   { CP_WAIT0(); }                             \
            __syncthreads();                                                   \
            if (kt + 3 < NIT) issue(kt + 3);                                   \
            const __half* pa = (sA) + (kt & 3) * (128 * 72);                   \
            const __half* pb = (sB) + (kt & 3) * (32 * 72);                    \
            _Pragma("unroll")                                                  \
            for (int ks = 0; ks < 4; ks++) {                                   \
                uint32_t a_[2][4], b_[4];                                      \
                _Pragma("unroll")                                              \
                for (int i = 0; i < 2; i++)                                    \
                    ldsm_x4(a_[i], smem_u32(pa + (wm_ * 32 + i * 16 + (lane_ & 15)) * 72 \
                                               + ks * 16 + (lane_ >> 4) * 8)); \
                ldsm_x4(b_, smem_u32(pb + (wn_ * 16 + (lane_ & 7) + ((lane_ >> 4) << 3)) * 72 \
                                        + ks * 16 + ((lane_ >> 3) & 1) * 8));  \
                _Pragma("unroll")                                              \
                for (int i = 0; i < 2; i++)                                    \
                    _Pragma("unroll")                                          \
                    for (int j = 0; j < 2; j++)                                \
                        mma16816(acc[i][j], a_[i], &b_[j * 2]);                \
            }                                                                  \
        }                                                                      \
    }

// Phase A: writes C[m*ldc + n0c+..] (+bias)
__device__ void phaseA_gemm(const __half* __restrict__ A, int lda, int K,
                            const __half* __restrict__ W, int ldw, int n0w,
                            const float* __restrict__ bias,
                            float* __restrict__ C, int ldc, int n0c,
                            __half* sA, __half* sB)
{
    PH_GEMM_CORE(A, lda, K, W, ldw, n0w, sA, sB);
    const int wid = threadIdx.x >> 5, lane = threadIdx.x & 31;
    const int wm = wid & 3, wn = wid >> 2;
#pragma unroll
    for (int i = 0; i < 2; i++) {
        int m = wm * 32 + i * 16 + (lane >> 2);
#pragma unroll
        for (int j = 0; j < 2; j++) {
            int n = n0c + wn * 16 + j * 8 + (lane & 3) * 2;
            float b0 = bias ? bias[n] : 0.f;
            float b1 = bias ? bias[n + 1] : 0.f;
            C[(size_t)m * ldc + n]           = acc[i][j][0] + b0;
            C[(size_t)m * ldc + n + 1]       = acc[i][j][1] + b1;
            C[(size_t)(m + 8) * ldc + n]     = acc[i][j][2] + b0;
            C[(size_t)(m + 8) * ldc + n + 1] = acc[i][j][3] + b1;
        }
    }
}

// Phase C: adds g_gates (h-part) and writes into smem exchange sG[128][33]
__device__ void phaseC_gemm(const __half* __restrict__ A, int lda, int K,
                            const __half* __restrict__ W, int ldw, int n0w,
                            float* __restrict__ sG,
                            __half* sA, __half* sB)
{
    PH_GEMM_CORE(A, lda, K, W, ldw, n0w, sA, sB);
    const int wid = threadIdx.x >> 5, lane = threadIdx.x & 31;
    const int wm = wid & 3, wn = wid >> 2;
#pragma unroll
    for (int i = 0; i < 2; i++) {
        int m = wm * 32 + i * 16 + (lane >> 2);
#pragma unroll
        for (int j = 0; j < 2; j++) {
            int w = wn * 16 + j * 8 + (lane & 3) * 2;
            int n = n0w + w;
            sG[m * 33 + w]           = acc[i][j][0] + g_gates[(size_t)m * 2048 + n];
            sG[m * 33 + w + 1]       = acc[i][j][1] + g_gates[(size_t)m * 2048 + n + 1];
            sG[(m + 8) * 33 + w]     = acc[i][j][2] + g_gates[(size_t)(m + 8) * 2048 + n];
            sG[(m + 8) * 33 + w + 1] = acc[i][j][3] + g_gates[(size_t)(m + 8) * 2048 + n + 1];
        }
    }
}

// =================== persistent fused scan kernel ===========================
// smem: sHp 26624 | sBH 53248 | sSC 2048 | sPh 2048 |
//       sA 4*128*72*2=73728 @83968 | sB 4*32*72*2=18432 @157696 | sG @176128
#define SMEM_SCAN 193024

__global__ __launch_bounds__(256)
void scan_kernel(const float* __restrict__ batch_H,
                 const float* __restrict__ score_W,
                 const float* __restrict__ h2h_b,
                 const int* __restrict__ text)
{
    extern __shared__ char dsm[];
    __half* sHp = (__half*)dsm;
    float*  sBH = (float*)(dsm + 26624);
    float*  sSC = (float*)(dsm + 79872);
    float*  sPh = (float*)(dsm + 81920);
    __half* sA  = (__half*)(dsm + 83968);
    __half* sB  = (__half*)(dsm + 157696);
    float*  sG  = (float*)(dsm + 176128);
    __shared__ float s_e[32];

    const int b   = blockIdx.x;
    const int tid = threadIdx.x;
    const int wid = tid >> 5, lane = tid & 31;

    // barrier counter base (persisted across graph replays; monotonic)
    int myc = (b == 0) ? g_relgen : g_flags[b];

    for (int i = tid; i < T_ * 512; i += 256) {
        sHp[i] = __float2half(g_Hproj[(size_t)b * T_ * 512 + i]);
        sBH[i] = batch_H[(size_t)b * T_ * 512 + i];
    }
#pragma unroll
    for (int i = 0; i < 2; i++) sSC[tid + 256 * i] = score_W[tid + 256 * i];
    __syncthreads();

    // LSTM cell state: CTA b<64 owns dims [8b, 8b+8) x 128 batches.
    float creg[4] = {0.f, 0.f, 0.f, 0.f};

    for (int s = 0; s < STEPS_; s++) {
        // ---- Phase A: Z = h @ [Whh_perm | h2h]^T (CTAs 0..79) ----
        if (b < 64)
            phaseA_gemm(g_xh + 512, 1024, 512, g_WA, 512, b * 32,
                        nullptr, g_gates, 2048, b * 32, sA, sB);
        else if (b < 80)
            phaseA_gemm(g_xh + 512, 1024, 512, g_WA, 512, b * 32,
                        h2h_b, g_ph, 512, b * 32 - 2048, sA, sB);
        myc++; grid_bar(b, myc);

        // ---- Phase B: attention for batch b ----
#pragma unroll
        for (int i = 0; i < 2; i++)
            sPh[tid + 256 * i] = g_ph[b * 512 + tid + 256 * i];
        __syncthreads();
        for (int t = wid; t < T_; t += 8) {
            const __half* hp = sHp + t * 512;
            float sum = 0.f;
            for (int j = lane; j < 512; j += 32)
                sum += sSC[j] * tanhf(__half2float(hp[j]) + sPh[j]);
#pragma unroll
            for (int o = 16; o > 0; o >>= 1)
                sum += __shfl_xor_sync(0xffffffffu, sum, o);
            if (lane == 0) s_e[t] = sum;
        }
        __syncthreads();
        if (tid < 32) {
            float v = (tid < T_) ? s_e[tid] : -1e30f;
            float m = v;
#pragma unroll
            for (int o = 16; o > 0; o >>= 1)
                m = fmaxf(m, __shfl_xor_sync(0xffffffffu, m, o));
            float e = (tid < T_) ? expf(v - m) : 0.f;
            float ssum = e;
#pragma unroll
            for (int o = 16; o > 0; o >>= 1)
                ssum += __shfl_xor_sync(0xffffffffu, ssum, o);
            if (tid < T_) s_e[tid] = e / ssum;
        }
        __syncthreads();
#pragma unroll
        for (int i = 0; i < 2; i++) {
            int j = tid + 256 * i;
            float acc = 0.f;
#pragma unroll
            for (int t = 0; t < T_; t++)
                acc += s_e[t] * sBH[t * 512 + j];
            g_xh[b * 1024 + j] = __float2half(acc);
        }
        myc++; grid_bar(b, myc);

        // ---- Phase C: gatesX = ctx @ Wih_perm^T + gatesH; fused LSTM ----
        if (b < 64) {
            phaseC_gemm(g_xh, 1024, 512, g_Wih_h, 512, b * 32, sG, sA, sB);
            __syncthreads();
            const int m = tid & 127, dg = tid >> 7;
            const int cls = text[m * STEPS_ + s];
            const float* wt = g_Wt + cls * 2048;
#pragma unroll
            for (int q = 0; q < 4; q++) {
                int dl = dg * 4 + q;
                int d = b * 8 + dl;
                float gi = sG[m * 33 + dl]       + wt[d];
                float gf = sG[m * 33 + 8 + dl]   + wt[512 + d];
                float gg = sG[m * 33 + 16 + dl]  + wt[1024 + d];
                float go = sG[m * 33 + 24 + dl]  + wt[1536 + d];
                float si = 1.f / (1.f + expf(-gi));
                float sf = 1.f / (1.f + expf(-gf));
                float so = 1.f / (1.f + expf(-go));
                float tg = tanhf(gg);
                float cn = sf * creg[q] + si * tg;
                creg[q] = cn;
                float hn = so * tanhf(cn);
                __half hh = __float2half(hn);
                g_xh[m * 1024 + 512 + d] = hh;
                g_Hs_h[((size_t)m * STEPS_ + s) * 512 + d] = hh;
            }
        }
        myc++; grid_bar(b, myc);
    }
}

// ============ head GEMM body (R9-proven): BM=128 BN=128 BK=64, 3-stage =====
#define HD_SMEM (6 * 128 * 72 * 2)   // 110592 bytes

__device__ __forceinline__ void head_body(
    const __half* __restrict__ A, const __half* __restrict__ W,
    const float* __restrict__ bias, float* __restrict__ out,
    int Ntot, int m0, int n0, __half* sA, __half* sB)
{
    const int tid = threadIdx.x;
    const int wid = tid >> 5, lane = tid & 31;
    const int wm = wid >> 2, wn = wid & 3;     // 2 x 4 warp grid

    float acc[4][4][4];
#pragma unroll
    for (int i = 0; i < 4; i++)
#pragma unroll
        for (int j = 0; j < 4; j++)
#pragma unroll
            for (int q = 0; q < 4; q++) acc[i][j][q] = 0.f;

#define HD_ISSUE(kt) do {                                                      \
        int st = (kt) % 3;                                                     \
        int k0 = (kt) << 6;                                                    \
        __half* pa = sA + st * (128 * 72);                                     \
        __half* pb = sB + st * (128 * 72);                                     \
        _Pragma("unroll")                                                      \
        for (int c = 0; c < 4; c++) {                                          \
            int idx = tid + 256 * c;                                           \
            int row = idx >> 3, q = (idx & 7) * 8;                             \
            cp_async16(smem_u32(pa + row * 72 + q),                            \
                       A + (size_t)(m0 + row) * 512 + k0 + q, 16);             \
            cp_async16(smem_u32(pb + row * 72 + q),                            \
                       W + (size_t)(n0 + row) * 512 + k0 + q,                  \
                       (n0 + row < Ntot) ? 16 : 0);                            \
        }                                                                      \
        CP_COMMIT();                                                           \
    } while (0)

    HD_ISSUE(0);
    HD_ISSUE(1);
    for (int kt = 0; kt < 8; kt++) {
        if (kt < 7) { CP_WAIT1(); } else { CP_WAIT0(); }
        __syncthreads();
        if (kt + 2 < 8) HD_ISSUE(kt + 2);
        const __half* pa = sA + (kt % 3) * (128 * 72);
        const __half* pb = sB + (kt % 3) * (128 * 72);
#pragma unroll
        for (int ks = 0; ks < 4; ks++) {
            uint32_t a[4][4], bfr[2][4];
#pragma unroll
            for (int i = 0; i < 4; i++)
                ldsm_x4(a[i], smem_u32(pa + (wm * 64 + i * 16 + (lane & 15)) * 72
                                          + ks * 16 + (lane >> 4) * 8));
#pragma unroll
            for (int j = 0; j < 2; j++)
                ldsm_x4(bfr[j], smem_u32(pb + (wn * 32 + j * 16 + (lane & 7)
                                              + ((lane >> 4) << 3)) * 72
                                            + ks * 16 + ((lane >> 3) & 1) * 8));
#pragma unroll
            for (int i = 0; i < 4; i++)
#pragma unroll
                for (int j = 0; j < 4; j++)
                    mma16816(acc[i][j], a[i], &bfr[j >> 1][(j & 1) * 2]);
        }
    }
#undef HD_ISSUE

#pragma unroll
    for (int i = 0; i < 4; i++) {
        int mBase = m0 + wm * 64 + i * 16 + (lane >> 2);
#pragma unroll
        for (int j = 0; j < 4; j++) {
            int n = n0 + wn * 32 + j * 8 + (lane & 3) * 2;
            if (n < Ntot) {
                float b0 = bias[n];
                float b1 = (n + 1 < Ntot) ? bias[n + 1] : 0.f;
                float* p0 = out + (size_t)mBase * Ntot + n;
                float* p1 = out + (size_t)(mBase + 8) * Ntot + n;
                p0[0] = acc[i][j][0] + b0;
                p1[0] = acc[i][j][2] + b0;
                if (n + 1 < Ntot) {
                    p0[1] = acc[i][j][1] + b1;
                    p1[1] = acc[i][j][3] + b1;
                }
            }
        }
    }
}

__global__ __launch_bounds__(256, 2)
void head_gemm_mma(const __half* __restrict__ A, const __half* __restrict__ W,
                   const float* __restrict__ bias, float* __restrict__ out,
                   int Ntot)
{
    extern __shared__ __half hsm[];
    head_body(A, W, bias, out, Ntot, blockIdx.x * 128, blockIdx.y * 128,
              hsm, hsm + 3 * 128 * 72);
}

__global__ __launch_bounds__(256, 2)
void head_gemm_multi(const __half* __restrict__ A,
                     const __half* W0, const float* b0, float* o0, int N0,
                     const __half* W1, const float* b1, float* o1, int N1,
                     const __half* W2, const float* b2, float* o2, int N2,
                     int y1, int y2)
{
    extern __shared__ __half hsm[];
    const int y = blockIdx.y;
    const __half* W; const float* bias; float* out; int Ntot, n0;
    if (y < y1)      { W = W0; bias = b0; out = o0; Ntot = N0; n0 = y * 128; }
    else if (y < y2) { W = W1; bias = b1; out = o1; Ntot = N1; n0 = (y - y1) * 128; }
    else             { W = W2; bias = b2; out = o2; Ntot = N2; n0 = (y - y2) * 128; }
    head_body(A, W, bias, out, Ntot, blockIdx.x * 128, n0,
              hsm, hsm + 3 * 128 * 72);
}

// ---------------- fused prep kernel (segments by blockIdx.x) ---------------
// [0,512): zero g_xh | [512,5632): build WA | [5632,9728): build Wih_h |
// [9728,9766): build Wt | [9766,10022): i2h->fp16 | [10022,11686): batch_H->fp16
__global__ void prep_kernel(const float* __restrict__ h2h_W,
                            const float* __restrict__ Wih,
                            const float* __restrict__ Whh,
                            const float* __restrict__ bih,
                            const float* __restrict__ bhh,
                            const float* __restrict__ i2h_W,
                            const float* __restrict__ batch_H)
{
    const int blk = blockIdx.x, tid = threadIdx.x;
    if (blk < 512) {
        g_xh[blk * 256 + tid] = __float2half(0.f);
    } else if (blk < 5632) {
        int i = (blk - 512) * 256 + tid;               // 2560*512 elems
        int r = i >> 9, k = i & 511;
        float v;
        if (r < 2048) {
            int grp = r >> 5, w = r & 31;
            int orig = ((w >> 3) << 9) + (grp << 3) + (w & 7);
            v = Whh[(size_t)orig * 512 + k];
        } else {
            v = h2h_W[(size_t)(r - 2048) * 512 + k];
        }
        g_WA[(size_t)r * 512 + k] = __float2half(v);
    } else if (blk < 9728) {
        int i = (blk - 5632) * 256 + tid;              // 2048*512 elems
        int r = i >> 9, k = i & 511;
        int grp = r >> 5, w = r & 31;
        int orig = ((w >> 3) << 9) + (grp << 3) + (w & 7);
        g_Wih_h[(size_t)r * 512 + k] = __float2half(Wih[(size_t)orig * 550 + k]);
    } else if (blk < 9766) {
        int c = blk - 9728;
        for (int n = tid; n < 2048; n += 256)
            g_Wt[c * 2048 + n] = Wih[(size_t)n * 550 + 512 + c] + bih[n] + bhh[n];
    } else if (blk < 10022) {
        int i = (blk - 9766) * 256 + tid;              // n4 = 65536
        float4 v = ((const float4*)i2h_W)[i];
        ((__half2*)g_i2h_h)[2 * i]     = __floats2half2_rn(v.x, v.y);
        ((__half2*)g_i2h_h)[2 * i + 1] = __floats2half2_rn(v.z, v.w);
    } else {
        int i = (blk - 10022) * 256 + tid;             // n4 = 425984
        if (i < 425984) {
            float4 v = ((const float4*)batch_H)[i];
            ((__half2*)g_bh_h)[2 * i]     = __floats2half2_rn(v.x, v.y);
            ((__half2*)g_bh_h)[2 * i + 1] = __floats2half2_rn(v.z, v.w);
        }
    }
}

__global__ void cvt_half(const float* __restrict__ src, __half* __restrict__ dst, int n4) {
    int i = blockIdx.x * blockDim.x + threadIdx.x;
    if (i < n4) {
        float4 v = ((const float4*)src)[i];
        ((__half2*)dst)[2 * i]     = __floats2half2_rn(v.x, v.y);
        ((__half2*)dst)[2 * i + 1] = __floats2half2_rn(v.z, v.w);
    }
}

// ---------------- launcher ----------------
extern "C" void kernel_launch(void* const* d_in, const int* in_sizes, int n_in,
                              void* d_out, int out_size)
{
    const float* batch_H = (const float*)d_in[0];
    const int*   text    = (const int*)  d_in[1];
    const float* i2h_W   = (const float*)d_in[2];
    const float* h2h_W   = (const float*)d_in[3];
    const float* h2h_b   = (const float*)d_in[4];
    const float* score_W = (const float*)d_in[5];
    const float* rnn_Wih = (const float*)d_in[6];
    const float* rnn_bih = (const float*)d_in[7];
    const float* rnn_Whh = (const float*)d_in[8];
    const float* rnn_bhh = (const float*)d_in[9];
    const float* char_W  = (const float*)d_in[10];
    const float* char_b  = (const float*)d_in[11];
    const float* bpe_W   = (const float*)d_in[12];
    const float* bpe_b   = (const float*)d_in[13];
    const float* wp_W    = (const float*)d_in[14];
    const float* wp_b    = (const float*)d_in[15];
    float* out = (float*)d_out;

    float *d_Hproj, *d_zeros;
    __half *d_Hs_h, *d_char_h, *d_bpe_h, *d_wp_h, *d_i2h_h, *d_bh_h;
    cudaGetSymbolAddress((void**)&d_Hproj,  g_Hproj);
    cudaGetSymbolAddress((void**)&d_Hs_h,   g_Hs_h);
    cudaGetSymbolAddress((void**)&d_char_h, g_char_h);
    cudaGetSymbolAddress((void**)&d_bpe_h,  g_bpe_h);
    cudaGetSymbolAddress((void**)&d_wp_h,   g_wp_h);
    cudaGetSymbolAddress((void**)&d_i2h_h,  g_i2h_h);
    cudaGetSymbolAddress((void**)&d_bh_h,   g_bh_h);
    cudaGetSymbolAddress((void**)&d_zeros,  g_zeros);

    cudaFuncSetAttribute(scan_kernel,
                         cudaFuncAttributeMaxDynamicSharedMemorySize, SMEM_SCAN);
    cudaFuncSetAttribute(head_gemm_mma,
                         cudaFuncAttributeMaxDynamicSharedMemorySize, HD_SMEM);
    cudaFuncSetAttribute(head_gemm_multi,
                         cudaFuncAttributeMaxDynamicSharedMemorySize, HD_SMEM);

    // 1) fused prep
    prep_kernel<<<11686, 256>>>(h2h_W, rnn_Wih, rnn_Whh, rnn_bih, rnn_bhh,
                                i2h_W, batch_H);
    // 2) Hproj = batch_H @ i2h^T via fp16 mma (zero bias)
    head_gemm_mma<<<dim3(26, 4), 256, HD_SMEM>>>(d_bh_h, d_i2h_h, d_zeros,
                                                 d_Hproj, 512);
    // 3) bpe weights -> fp16 (keeps scan as 4th launch for ncu)
    cvt_half<<<(BPE_ * H_ / 4 + 255) / 256, 256>>>(bpe_W, d_bpe_h, BPE_ * H_ / 4);
    // 4) fused persistent scan (profiled launch)
    scan_kernel<<<GRID_SCAN, 256, SMEM_SCAN>>>(batch_H, score_W, h2h_b, text);
    // 5-6) remaining weight conversions
    cvt_half<<<(NC_ * H_ / 4 + 255) / 256, 256>>>(char_W, d_char_h, NC_ * H_ / 4);
    cvt_half<<<(WP_ * H_ / 4 + 255) / 256, 256>>>(wp_W, d_wp_h, WP_ * H_ / 4);

    // 7) all three heads in one launch: [bpe | wp | char]
    const long long off_bpe = (long long)ROWS_ * NC_;
    const long long off_wp  = off_bpe + (long long)ROWS_ * BPE_;
    const int y_bpe = (BPE_ + 127) / 128;          // 393
    const int y_wp  = (WP_ + 127) / 128;           // 239
    head_gemm_multi<<<dim3(26, y_bpe + y_wp + 1), 256, HD_SMEM>>>(
        d_Hs_h,
        d_bpe_h,  bpe_b,  out + off_bpe, BPE_,
        d_wp_h,   wp_b,   out + off_wp,  WP_,
        d_char_h, char_b, out,           NC_,
        y_bpe, y_bpe + y_wp);
}

// round 16
// speedup vs baseline: 1.0299x; 1.0299x over previous
#include <cuda_runtime.h>
#include <cuda_fp16.h>
#include <cstdint>

// Problem constants
#define B_     128
#define T_     26
#define IN_    512
#define H_     512
#define NC_    38
#define STEPS_ 26
#define BPE_   50257
#define WP_    30522
#define ROWS_  (B_ * STEPS_)   // 3328
#define GRID_SCAN 128

// ---------------- device scratch ----------------
__device__ float g_Hproj[ROWS_ * H_];                  // i2h(batch_H) fp32
__device__ float g_ph[B_ * H_];                        // h @ h2h^T + b
__device__ float g_gates[B_ * 4 * H_];                 // h-part of gates (perm rows)
__device__ __align__(16) __half g_xh[B_ * 1024];       // [ctx | h] fp16 per batch
__device__ __align__(16) __half g_WA[2560 * 512];      // [Whh_perm | h2h] fp16
__device__ __align__(16) __half g_Wih_h[2048 * 512];   // Wih(:,:512) perm rows fp16
__device__ float g_Wt[NC_ * 4 * H_];                   // onehot col + bih + bhh (orig layout)
__device__ __align__(16) __half g_Hs_h[ROWS_ * H_];    // hidden states fp16
__device__ __align__(16) __half g_char_h[NC_ * H_];
__device__ __align__(16) __half g_bpe_h[(size_t)BPE_ * H_];
__device__ __align__(16) __half g_wp_h[(size_t)WP_ * H_];
__device__ __align__(16) __half g_i2h_h[H_ * IN_];     // i2h fp16
__device__ __align__(16) __half g_bh_h[ROWS_ * IN_];   // batch_H fp16
__device__ float g_zeros[512];                         // zero-init, never written

// grid barrier state (R12-proven atomic counter)
__device__ int g_bar_cnt = 0;
__device__ volatile int g_bar_gen = 0;
// ph producer flags (monotonic counters; 16 producers = CTAs 64..79)
__device__ volatile int g_ph_flags[16];

// ======================= helpers =================
__device__ __forceinline__ uint32_t smem_u32(const void* p) {
    return (uint32_t)__cvta_generic_to_shared(p);
}
__device__ __forceinline__ void cp_async16(uint32_t dst, const void* src, int src_bytes) {
    asm volatile("cp.async.cg.shared.global [%0], [%1], 16, %2;"
                 :: "r"(dst), "l"(src), "r"(src_bytes));
}
#define CP_COMMIT() asm volatile("cp.async.commit_group;" ::: "memory")
#define CP_WAIT0()  asm volatile("cp.async.wait_group 0;" ::: "memory")
#define CP_WAIT1()  asm volatile("cp.async.wait_group 1;" ::: "memory")
#define CP_WAIT2()  asm volatile("cp.async.wait_group 2;" ::: "memory")

__device__ __forceinline__ void ldsm_x4(uint32_t* r, uint32_t addr) {
    asm volatile("ldmatrix.sync.aligned.m8n8.x4.shared.b16 {%0,%1,%2,%3}, [%4];"
                 : "=r"(r[0]), "=r"(r[1]), "=r"(r[2]), "=r"(r[3]) : "r"(addr));
}
__device__ __forceinline__ void mma16816(float* d, const uint32_t* a, const uint32_t* b) {
    asm volatile(
        "mma.sync.aligned.m16n8k16.row.col.f32.f16.f16.f32 "
        "{%0,%1,%2,%3}, {%4,%5,%6,%7}, {%8,%9}, {%0,%1,%2,%3};"
        : "+f"(d[0]), "+f"(d[1]), "+f"(d[2]), "+f"(d[3])
        : "r"(a[0]), "r"(a[1]), "r"(a[2]), "r"(a[3]), "r"(b[0]), "r"(b[1]));
}

// R12-proven atomic-counter grid barrier
__device__ __forceinline__ void grid_bar() {
    __syncthreads();
    if (threadIdx.x == 0) {
        __threadfence();
        int gen = g_bar_gen;
        if (atomicAdd(&g_bar_cnt, 1) == GRID_SCAN - 1) {
            g_bar_cnt = 0;
            __threadfence();
            g_bar_gen = gen + 1;
        } else {
            while (g_bar_gen == gen) {}
        }
        __threadfence();
    }
    __syncthreads();
}

// ====== GEMM core macro: A[128,K]h (lda), W rows n0w..n0w+32 (ldw) =========
// 4-stage cp.async, issue-3-ahead, single sync per iteration.
#define PH_GEMM_CORE(Aptr, lda, K, Wptr, ldw, n0w, sA, sB)                     \
    float acc[2][2][4];                                                        \
    _Pragma("unroll")                                                          \
    for (int i = 0; i < 2; i++)                                                \
        _Pragma("unroll")                                                      \
        for (int j = 0; j < 2; j++)                                            \
            _Pragma("unroll")                                                  \
            for (int q = 0; q < 4; q++) acc[i][j][q] = 0.f;                    \
    {                                                                          \
        const int NIT = (K) >> 6;                                              \
        const int tid_ = threadIdx.x;                                          \
        const int wid_ = tid_ >> 5, lane_ = tid_ & 31;                         \
        const int wm_ = wid_ & 3, wn_ = wid_ >> 2;                             \
        auto issue = [&](int kt) {                                             \
            int st = kt & 3;                                                   \
            int k0 = kt << 6;                                                  \
            __half* pa = (sA) + st * (128 * 72);                               \
            __half* pb = (sB) + st * (32 * 72);                                \
            _Pragma("unroll")                                                  \
            for (int c = 0; c < 4; c++) {                                      \
                int idx = tid_ + 256 * c;                                      \
                int row = idx >> 3, q = (idx & 7) * 8;                         \
                cp_async16(smem_u32(pa + row * 72 + q),                        \
                           (Aptr) + (size_t)row * (lda) + k0 + q, 16);         \
            }                                                                  \
            { int row = tid_ >> 3, q = (tid_ & 7) * 8;                         \
              cp_async16(smem_u32(pb + row * 72 + q),                          \
                         (Wptr) + (size_t)((n0w) + row) * (ldw) + k0 + q, 16); } \
            CP_COMMIT();                                                       \
        };                                                                     \
        issue(0); issue(1); issue(2);                                          \
        for (int kt = 0; kt < NIT; kt++) {                                     \
            if (kt < NIT - 2)      { CP_WAIT2(); }                             \
            else if (kt == NIT - 2){ CP_WAIT1(); }                             \
            else                   { CP_WAIT0(); }                             \
            __syncthreads();                                                   \
            if (kt + 3 < NIT) issue(kt + 3);                                   \
            const __half* pa = (sA) + (kt & 3) * (128 * 72);                   \
            const __half* pb = (sB) + (kt & 3) * (32 * 72);                    \
            _Pragma("unroll")                                                  \
            for (int ks = 0; ks < 4; ks++) {                                   \
                uint32_t a_[2][4], b_[4];                                      \
                _Pragma("unroll")                                              \
                for (int i = 0; i < 2; i++)                                    \
                    ldsm_x4(a_[i], smem_u32(pa + (wm_ * 32 + i * 16 + (lane_ & 15)) * 72 \
                                               + ks * 16 + (lane_ >> 4) * 8)); \
                ldsm_x4(b_, smem_u32(pb + (wn_ * 16 + (lane_ & 7) + ((lane_ >> 4) << 3)) * 72 \
                                        + ks * 16 + ((lane_ >> 3) & 1) * 8));  \
                _Pragma("unroll")                                              \
                for (int i = 0; i < 2; i++)                                    \
                    _Pragma("unroll")                                          \
                    for (int j = 0; j < 2; j++)                                \
                        mma16816(acc[i][j], a_[i], &b_[j * 2]);                \
            }                                                                  \
        }                                                                      \
    }

// Phase A: writes C[m*ldc + n0c+..] (+bias)
__device__ void phaseA_gemm(const __half* __restrict__ A, int lda, int K,
                            const __half* __restrict__ W, int ldw, int n0w,
                            const float* __restrict__ bias,
                            float* __restrict__ C, int ldc, int n0c,
                            __half* sA, __half* sB)
{
    PH_GEMM_CORE(A, lda, K, W, ldw, n0w, sA, sB);
    const int wid = threadIdx.x >> 5, lane = threadIdx.x & 31;
    const int wm = wid & 3, wn = wid >> 2;
#pragma unroll
    for (int i = 0; i < 2; i++) {
        int m = wm * 32 + i * 16 + (lane >> 2);
#pragma unroll
        for (int j = 0; j < 2; j++) {
            int n = n0c + wn * 16 + j * 8 + (lane & 3) * 2;
            float b0 = bias ? bias[n] : 0.f;
            float b1 = bias ? bias[n + 1] : 0.f;
            C[(size_t)m * ldc + n]           = acc[i][j][0] + b0;
            C[(size_t)m * ldc + n + 1]       = acc[i][j][1] + b1;
            C[(size_t)(m + 8) * ldc + n]     = acc[i][j][2] + b0;
            C[(size_t)(m + 8) * ldc + n + 1] = acc[i][j][3] + b1;
        }
    }
}

// Phase C: adds g_gates (h-part) and writes into smem exchange sG[128][33]
__device__ void phaseC_gemm(const __half* __restrict__ A, int lda, int K,
                            const __half* __restrict__ W, int ldw, int n0w,
                            float* __restrict__ sG,
                            __half* sA, __half* sB)
{
    PH_GEMM_CORE(A, lda, K, W, ldw, n0w, sA, sB);
    const int wid = threadIdx.x >> 5, lane = threadIdx.x & 31;
    const int wm = wid & 3, wn = wid >> 2;
#pragma unroll
    for (int i = 0; i < 2; i++) {
        int m = wm * 32 + i * 16 + (lane >> 2);
#pragma unroll
        for (int j = 0; j < 2; j++) {
            int w = wn * 16 + j * 8 + (lane & 3) * 2;
            int n = n0w + w;
            sG[m * 33 + w]           = acc[i][j][0] + g_gates[(size_t)m * 2048 + n];
            sG[m * 33 + w + 1]       = acc[i][j][1] + g_gates[(size_t)m * 2048 + n + 1];
            sG[(m + 8) * 33 + w]     = acc[i][j][2] + g_gates[(size_t)(m + 8) * 2048 + n];
            sG[(m + 8) * 33 + w + 1] = acc[i][j][3] + g_gates[(size_t)(m + 8) * 2048 + n + 1];
        }
    }
}

// =================== persistent fused scan kernel ===========================
// smem: sHp 26624 | sBH 53248 | sSC 2048 | sPh 2048 |
//       sA 4*128*72*2=73728 @83968 | sB 4*32*72*2=18432 @157696 | sG @176128
#define SMEM_SCAN 193024

__global__ __launch_bounds__(256)
void scan_kernel(const float* __restrict__ batch_H,
                 const float* __restrict__ score_W,
                 const float* __restrict__ h2h_b,
                 const int* __restrict__ text)
{
    extern __shared__ char dsm[];
    __half* sHp = (__half*)dsm;
    float*  sBH = (float*)(dsm + 26624);
    float*  sSC = (float*)(dsm + 79872);
    float*  sPh = (float*)(dsm + 81920);
    __half* sA  = (__half*)(dsm + 83968);
    __half* sB  = (__half*)(dsm + 157696);
    float*  sG  = (float*)(dsm + 176128);
    __shared__ float s_e[32];
    __shared__ int s_phbase;

    const int b   = blockIdx.x;
    const int tid = threadIdx.x;
    const int wid = tid >> 5, lane = tid & 31;

    // ph flag base: all 16 flags are equal at launch start (monotonic,
    // persisted across graph replays; zero on first launch).
    if (tid == 0) s_phbase = g_ph_flags[0];

    for (int i = tid; i < T_ * 512; i += 256) {
        sHp[i] = __float2half(g_Hproj[(size_t)b * T_ * 512 + i]);
        sBH[i] = batch_H[(size_t)b * T_ * 512 + i];
    }
#pragma unroll
    for (int i = 0; i < 2; i++) sSC[tid + 256 * i] = score_W[tid + 256 * i];
    __syncthreads();
    const int phbase = s_phbase;

    // LSTM cell state: CTA b<64 owns dims [8b, 8b+8) x 128 batches.
    float creg[4] = {0.f, 0.f, 0.f, 0.f};

    for (int s = 0; s < STEPS_; s++) {
        const int phtgt = phbase + s + 1;

        // ---- Phase A: Z = h @ [Whh_perm | h2h]^T (CTAs 0..79) ----
        // gatesH (CTAs 0..63) is CTA-private until Phase C: no barrier needed.
        // ph (CTAs 64..79) is published via 16 monotonic flags.
        if (b < 64) {
            phaseA_gemm(g_xh + 512, 1024, 512, g_WA, 512, b * 32,
                        nullptr, g_gates, 2048, b * 32, sA, sB);
        } else if (b < 80) {
            phaseA_gemm(g_xh + 512, 1024, 512, g_WA, 512, b * 32,
                        h2h_b, g_ph, 512, b * 32 - 2048, sA, sB);
            __syncthreads();
            if (tid == 0) { __threadfence(); g_ph_flags[b - 64] = phtgt; }
        }

        // ---- ph-ready wait (replaces full barrier 1) ----
        if (tid < 16) { while (g_ph_flags[tid] < phtgt) {} }
        __syncthreads();
        if (tid == 0) __threadfence();   // acquire (L1 invalidate)
        __syncthreads();

        // ---- Phase B: attention for batch b ----
#pragma unroll
        for (int i = 0; i < 2; i++)
            sPh[tid + 256 * i] = g_ph[b * 512 + tid + 256 * i];
        __syncthreads();
        for (int t = wid; t < T_; t += 8) {
            const __half* hp = sHp + t * 512;
            float sum = 0.f;
            for (int j = lane; j < 512; j += 32)
                sum += sSC[j] * tanhf(__half2float(hp[j]) + sPh[j]);
#pragma unroll
            for (int o = 16; o > 0; o >>= 1)
                sum += __shfl_xor_sync(0xffffffffu, sum, o);
            if (lane == 0) s_e[t] = sum;
        }
        __syncthreads();
        if (tid < 32) {
            float v = (tid < T_) ? s_e[tid] : -1e30f;
            float m = v;
#pragma unroll
            for (int o = 16; o > 0; o >>= 1)
                m = fmaxf(m, __shfl_xor_sync(0xffffffffu, m, o));
            float e = (tid < T_) ? expf(v - m) : 0.f;
            float ssum = e;
#pragma unroll
            for (int o = 16; o > 0; o >>= 1)
                ssum += __shfl_xor_sync(0xffffffffu, ssum, o);
            if (tid < T_) s_e[tid] = e / ssum;
        }
        __syncthreads();
#pragma unroll
        for (int i = 0; i < 2; i++) {
            int j = tid + 256 * i;
            float acc = 0.f;
#pragma unroll
            for (int t = 0; t < T_; t++)
                acc += s_e[t] * sBH[t * 512 + j];
            g_xh[b * 1024 + j] = __float2half(acc);
        }
        grid_bar();   // full barrier: ctx (128 producers -> 64 consumers)

        // ---- Phase C: gatesX = ctx @ Wih_perm^T + gatesH; fused LSTM ----
        if (b < 64) {
            phaseC_gemm(g_xh, 1024, 512, g_Wih_h, 512, b * 32, sG, sA, sB);
            __syncthreads();
            const int m = tid & 127, dg = tid >> 7;
            const int cls = text[m * STEPS_ + s];
            const float* wt = g_Wt + cls * 2048;
#pragma unroll
            for (int q = 0; q < 4; q++) {
                int dl = dg * 4 + q;
                int d = b * 8 + dl;
                float gi = sG[m * 33 + dl]       + wt[d];
                float gf = sG[m * 33 + 8 + dl]   + wt[512 + d];
                float gg = sG[m * 33 + 16 + dl]  + wt[1024 + d];
                float go = sG[m * 33 + 24 + dl]  + wt[1536 + d];
                float si = 1.f / (1.f + expf(-gi));
                float sf = 1.f / (1.f + expf(-gf));
                float so = 1.f / (1.f + expf(-go));
                float tg = tanhf(gg);
                float cn = sf * creg[q] + si * tg;
                creg[q] = cn;
                float hn = so * tanhf(cn);
                __half hh = __float2half(hn);
                g_xh[m * 1024 + 512 + d] = hh;
                g_Hs_h[((size_t)m * STEPS_ + s) * 512 + d] = hh;
            }
        }
        grid_bar();   // full barrier: h (64 producers -> consumers of A/B)
    }
}

// ============ head GEMM body (R9-proven): BM=128 BN=128 BK=64, 3-stage =====
#define HD_SMEM (6 * 128 * 72 * 2)   // 110592 bytes

__device__ __forceinline__ void head_body(
    const __half* __restrict__ A, const __half* __restrict__ W,
    const float* __restrict__ bias, float* __restrict__ out,
    int Ntot, int m0, int n0, __half* sA, __half* sB)
{
    const int tid = threadIdx.x;
    const int wid = tid >> 5, lane = tid & 31;
    const int wm = wid >> 2, wn = wid & 3;     // 2 x 4 warp grid

    float acc[4][4][4];
#pragma unroll
    for (int i = 0; i < 4; i++)
#pragma unroll
        for (int j = 0; j < 4; j++)
#pragma unroll
            for (int q = 0; q < 4; q++) acc[i][j][q] = 0.f;

#define HD_ISSUE(kt) do {                                                      \
        int st = (kt) % 3;                                                     \
        int k0 = (kt) << 6;                                                    \
        __half* pa = sA + st * (128 * 72);                                     \
        __half* pb = sB + st * (128 * 72);                                     \
        _Pragma("unroll")                                                      \
        for (int c = 0; c < 4; c++) {                                          \
            int idx = tid + 256 * c;                                           \
            int row = idx >> 3, q = (idx & 7) * 8;                             \
            cp_async16(smem_u32(pa + row * 72 + q),                            \
                       A + (size_t)(m0 + row) * 512 + k0 + q, 16);             \
            cp_async16(smem_u32(pb + row * 72 + q),                            \
                       W + (size_t)(n0 + row) * 512 + k0 + q,                  \
                       (n0 + row < Ntot) ? 16 : 0);                            \
        }                                                                      \
        CP_COMMIT();                                                           \
    } while (0)

    HD_ISSUE(0);
    HD_ISSUE(1);
    for (int kt = 0; kt < 8; kt++) {
        if (kt < 7) { CP_WAIT1(); } else { CP_WAIT0(); }
        __syncthreads();
        if (kt + 2 < 8) HD_ISSUE(kt + 2);
        const __half* pa = sA + (kt % 3) * (128 * 72);
        const __half* pb = sB + (kt % 3) * (128 * 72);
#pragma unroll
        for (int ks = 0; ks < 4; ks++) {
            uint32_t a[4][4], bfr[2][4];
#pragma unroll
            for (int i = 0; i < 4; i++)
                ldsm_x4(a[i], smem_u32(pa + (wm * 64 + i * 16 + (lane & 15)) * 72
                                          + ks * 16 + (lane >> 4) * 8));
#pragma unroll
            for (int j = 0; j < 2; j++)
                ldsm_x4(bfr[j], smem_u32(pb + (wn * 32 + j * 16 + (lane & 7)
                                              + ((lane >> 4) << 3)) * 72
                                            + ks * 16 + ((lane >> 3) & 1) * 8));
#pragma unroll
            for (int i = 0; i < 4; i++)
#pragma unroll
                for (int j = 0; j < 4; j++)
                    mma16816(acc[i][j], a[i], &bfr[j >> 1][(j & 1) * 2]);
        }
    }
#undef HD_ISSUE

#pragma unroll
    for (int i = 0; i < 4; i++) {
        int mBase = m0 + wm * 64 + i * 16 + (lane >> 2);
#pragma unroll
        for (int j = 0; j < 4; j++) {
            int n = n0 + wn * 32 + j * 8 + (lane & 3) * 2;
            if (n < Ntot) {
                float b0 = bias[n];
                float b1 = (n + 1 < Ntot) ? bias[n + 1] : 0.f;
                float* p0 = out + (size_t)mBase * Ntot + n;
                float* p1 = out + (size_t)(mBase + 8) * Ntot + n;
                p0[0] = acc[i][j][0] + b0;
                p1[0] = acc[i][j][2] + b0;
                if (n + 1 < Ntot) {
                    p0[1] = acc[i][j][1] + b1;
                    p1[1] = acc[i][j][3] + b1;
                }
            }
        }
    }
}

__global__ __launch_bounds__(256, 2)
void head_gemm_mma(const __half* __restrict__ A, const __half* __restrict__ W,
                   const float* __restrict__ bias, float* __restrict__ out,
                   int Ntot)
{
    extern __shared__ __half hsm[];
    head_body(A, W, bias, out, Ntot, blockIdx.x * 128, blockIdx.y * 128,
              hsm, hsm + 3 * 128 * 72);
}

__global__ __launch_bounds__(256, 2)
void head_gemm_multi(const __half* __restrict__ A,
                     const __half* W0, const float* b0, float* o0, int N0,
                     const __half* W1, const float* b1, float* o1, int N1,
                     const __half* W2, const float* b2, float* o2, int N2,
                     int y1, int y2)
{
    extern __shared__ __half hsm[];
    const int y = blockIdx.y;
    const __half* W; const float* bias; float* out; int Ntot, n0;
    if (y < y1)      { W = W0; bias = b0; out = o0; Ntot = N0; n0 = y * 128; }
    else if (y < y2) { W = W1; bias = b1; out = o1; Ntot = N1; n0 = (y - y1) * 128; }
    else             { W = W2; bias = b2; out = o2; Ntot = N2; n0 = (y - y2) * 128; }
    head_body(A, W, bias, out, Ntot, blockIdx.x * 128, n0,
              hsm, hsm + 3 * 128 * 72);
}

// ---------------- fused prep kernel (segments by blockIdx.x) ---------------
// [0,512): zero g_xh | [512,5632): build WA | [5632,9728): build Wih_h |
// [9728,9766): build Wt | [9766,10022): i2h->fp16 | [10022,11686): batch_H->fp16
__global__ void prep_kernel(const float* __restrict__ h2h_W,
                            const float* __restrict__ Wih,
                            const float* __restrict__ Whh,
                            const float* __restrict__ bih,
                            const float* __restrict__ bhh,
                            const float* __restrict__ i2h_W,
                            const float* __restrict__ batch_H)
{
    const int blk = blockIdx.x, tid = threadIdx.x;
    if (blk < 512) {
        g_xh[blk * 256 + tid] = __float2half(0.f);
    } else if (blk < 5632) {
        int i = (blk - 512) * 256 + tid;               // 2560*512 elems
        int r = i >> 9, k = i & 511;
        float v;
        if (r < 2048) {
            int grp = r >> 5, w = r & 31;
            int orig = ((w >> 3) << 9) + (grp << 3) + (w & 7);
            v = Whh[(size_t)orig * 512 + k];
        } else {
            v = h2h_W[(size_t)(r - 2048) * 512 + k];
        }
        g_WA[(size_t)r * 512 + k] = __float2half(v);
    } else if (blk < 9728) {
        int i = (blk - 5632) * 256 + tid;              // 2048*512 elems
        int r = i >> 9, k = i & 511;
        int grp = r >> 5, w = r & 31;
        int orig = ((w >> 3) << 9) + (grp << 3) + (w & 7);
        g_Wih_h[(size_t)r * 512 + k] = __float2half(Wih[(size_t)orig * 550 + k]);
    } else if (blk < 9766) {
        int c = blk - 9728;
        for (int n = tid; n < 2048; n += 256)
            g_Wt[c * 2048 + n] = Wih[(size_t)n * 550 + 512 + c] + bih[n] + bhh[n];
    } else if (blk < 10022) {
        int i = (blk - 9766) * 256 + tid;              // n4 = 65536
        float4 v = ((const float4*)i2h_W)[i];
        ((__half2*)g_i2h_h)[2 * i]     = __floats2half2_rn(v.x, v.y);
        ((__half2*)g_i2h_h)[2 * i + 1] = __floats2half2_rn(v.z, v.w);
    } else {
        int i = (blk - 10022) * 256 + tid;             // n4 = 425984
        if (i < 425984) {
            float4 v = ((const float4*)batch_H)[i];
            ((__half2*)g_bh_h)[2 * i]     = __floats2half2_rn(v.x, v.y);
            ((__half2*)g_bh_h)[2 * i + 1] = __floats2half2_rn(v.z, v.w);
        }
    }
}

__global__ void cvt_half(const float* __restrict__ src, __half* __restrict__ dst, int n4) {
    int i = blockIdx.x * blockDim.x + threadIdx.x;
    if (i < n4) {
        float4 v = ((const float4*)src)[i];
        ((__half2*)dst)[2 * i]     = __floats2half2_rn(v.x, v.y);
        ((__half2*)dst)[2 * i + 1] = __floats2half2_rn(v.z, v.w);
    }
}

// ---------------- launcher ----------------
extern "C" void kernel_launch(void* const* d_in, const int* in_sizes, int n_in,
                              void* d_out, int out_size)
{
    const float* batch_H = (const float*)d_in[0];
    const int*   text    = (const int*)  d_in[1];
    const float* i2h_W   = (const float*)d_in[2];
    const float* h2h_W   = (const float*)d_in[3];
    const float* h2h_b   = (const float*)d_in[4];
    const float* score_W = (const float*)d_in[5];
    const float* rnn_Wih = (const float*)d_in[6];
    const float* rnn_bih = (const float*)d_in[7];
    const float* rnn_Whh = (const float*)d_in[8];
    const float* rnn_bhh = (const float*)d_in[9];
    const float* char_W  = (const float*)d_in[10];
    const float* char_b  = (const float*)d_in[11];
    const float* bpe_W   = (const float*)d_in[12];
    const float* bpe_b   = (const float*)d_in[13];
    const float* wp_W    = (const float*)d_in[14];
    const float* wp_b    = (const float*)d_in[15];
    float* out = (float*)d_out;

    float *d_Hproj, *d_zeros;
    __half *d_Hs_h, *d_char_h, *d_bpe_h, *d_wp_h, *d_i2h_h, *d_bh_h;
    cudaGetSymbolAddress((void**)&d_Hproj,  g_Hproj);
    cudaGetSymbolAddress((void**)&d_Hs_h,   g_Hs_h);
    cudaGetSymbolAddress((void**)&d_char_h, g_char_h);
    cudaGetSymbolAddress((void**)&d_bpe_h,  g_bpe_h);
    cudaGetSymbolAddress((void**)&d_wp_h,   g_wp_h);
    cudaGetSymbolAddress((void**)&d_i2h_h,  g_i2h_h);
    cudaGetSymbolAddress((void**)&d_bh_h,   g_bh_h);
    cudaGetSymbolAddress((void**)&d_zeros,  g_zeros);

    cudaFuncSetAttribute(scan_kernel,
                         cudaFuncAttributeMaxDynamicSharedMemorySize, SMEM_SCAN);
    cudaFuncSetAttribute(head_gemm_mma,
                         cudaFuncAttributeMaxDynamicSharedMemorySize, HD_SMEM);
    cudaFuncSetAttribute(head_gemm_multi,
                         cudaFuncAttributeMaxDynamicSharedMemorySize, HD_SMEM);

    // 1) fused prep
    prep_kernel<<<11686, 256>>>(h2h_W, rnn_Wih, rnn_Whh, rnn_bih, rnn_bhh,
                                i2h_W, batch_H);
    // 2) Hproj = batch_H @ i2h^T via fp16 mma (zero bias)
    head_gemm_mma<<<dim3(26, 4), 256, HD_SMEM>>>(d_bh_h, d_i2h_h, d_zeros,
                                                 d_Hproj, 512);
    // 3) bpe weights -> fp16 (keeps scan as 4th launch for ncu)
    cvt_half<<<(BPE_ * H_ / 4 + 255) / 256, 256>>>(bpe_W, d_bpe_h, BPE_ * H_ / 4);
    // 4) fused persistent scan (profiled launch)
    scan_kernel<<<GRID_SCAN, 256, SMEM_SCAN>>>(batch_H, score_W, h2h_b, text);
    // 5-6) remaining weight conversions
    cvt_half<<<(NC_ * H_ / 4 + 255) / 256, 256>>>(char_W, d_char_h, NC_ * H_ / 4);
    cvt_half<<<(WP_ * H_ / 4 + 255) / 256, 256>>>(wp_W, d_wp_h, WP_ * H_ / 4);

    // 7) all three heads in one launch: [bpe | wp | char]
    const long long off_bpe = (long long)ROWS_ * NC_;
    const long long off_wp  = off_bpe + (long long)ROWS_ * BPE_;
    const int y_bpe = (BPE_ + 127) / 128;          // 393
    const int y_wp  = (WP_ + 127) / 128;           // 239
    head_gemm_multi<<<dim3(26, y_bpe + y_wp + 1), 256, HD_SMEM>>>(
        d_Hs_h,
        d_bpe_h,  bpe_b,  out + off_bpe, BPE_,
        d_wp_h,   wp_b,   out + off_wp,  WP_,
        d_char_h, char_b, out,           NC_,
        y_bpe, y_bpe + y_wp);
}

// round 17
// speedup vs baseline: 1.0485x; 1.0180x over previous
#include <cuda_runtime.h>
#include <cuda_fp16.h>
#include <cstdint>

// Problem constants
#define B_     128
#define T_     26
#define IN_    512
#define H_     512
#define NC_    38
#define STEPS_ 26
#define BPE_   50257
#define WP_    30522
#define ROWS_  (B_ * STEPS_)   // 3328
#define GRID_SCAN 128

// ---------------- device scratch ----------------
__device__ float g_Hproj[ROWS_ * H_];                  // i2h(batch_H) fp32
__device__ float g_ph[B_ * H_];                        // h @ h2h^T + b
__device__ float g_gates[B_ * 4 * H_];                 // h-part of gates (perm rows)
__device__ __align__(16) __half g_xh[B_ * 1024];       // [ctx | h] fp16 per batch
__device__ __align__(16) __half g_WA[2560 * 512];      // [Whh_perm | h2h] fp16
__device__ __align__(16) __half g_Wih_h[2048 * 512];   // Wih(:,:512) perm rows fp16
__device__ float g_Wt[NC_ * 4 * H_];                   // onehot col + bih + bhh (orig layout)
__device__ __align__(16) __half g_Hs_h[ROWS_ * H_];    // hidden states fp16
__device__ __align__(16) __half g_char_h[NC_ * H_];
__device__ __align__(16) __half g_bpe_h[(size_t)BPE_ * H_];
__device__ __align__(16) __half g_wp_h[(size_t)WP_ * H_];
__device__ __align__(16) __half g_i2h_h[H_ * IN_];     // i2h fp16
__device__ __align__(16) __half g_bh_h[ROWS_ * IN_];   // batch_H fp16
__device__ float g_zeros[512];                         // zero-init, never written

// grid barrier state (R12-proven atomic counter)
__device__ int g_bar_cnt = 0;
__device__ volatile int g_bar_gen = 0;

// ======================= helpers =================
__device__ __forceinline__ uint32_t smem_u32(const void* p) {
    return (uint32_t)__cvta_generic_to_shared(p);
}
__device__ __forceinline__ void cp_async16(uint32_t dst, const void* src, int src_bytes) {
    asm volatile("cp.async.cg.shared.global [%0], [%1], 16, %2;"
                 :: "r"(dst), "l"(src), "r"(src_bytes));
}
#define CP_COMMIT() asm volatile("cp.async.commit_group;" ::: "memory")
#define CP_WAIT0()  asm volatile("cp.async.wait_group 0;" ::: "memory")
#define CP_WAIT1()  asm volatile("cp.async.wait_group 1;" ::: "memory")
#define CP_WAIT2()  asm volatile("cp.async.wait_group 2;" ::: "memory")

__device__ __forceinline__ void ldsm_x4(uint32_t* r, uint32_t addr) {
    asm volatile("ldmatrix.sync.aligned.m8n8.x4.shared.b16 {%0,%1,%2,%3}, [%4];"
                 : "=r"(r[0]), "=r"(r[1]), "=r"(r[2]), "=r"(r[3]) : "r"(addr));
}
__device__ __forceinline__ void mma16816(float* d, const uint32_t* a, const uint32_t* b) {
    asm volatile(
        "mma.sync.aligned.m16n8k16.row.col.f32.f16.f16.f32 "
        "{%0,%1,%2,%3}, {%4,%5,%6,%7}, {%8,%9}, {%0,%1,%2,%3};"
        : "+f"(d[0]), "+f"(d[1]), "+f"(d[2]), "+f"(d[3])
        : "r"(a[0]), "r"(a[1]), "r"(a[2]), "r"(a[3]), "r"(b[0]), "r"(b[1]));
}

// hardware tanh (sm_75+): single MUFU op, max rel err ~2^-11 (same scale as
// the fp16 rounding already applied to its inputs)
__device__ __forceinline__ float tanh_fast(float x) {
    float y;
    asm("tanh.approx.f32 %0, %1;" : "=f"(y) : "f"(x));
    return y;
}

// R12-proven atomic-counter grid barrier
__device__ __forceinline__ void grid_bar() {
    __syncthreads();
    if (threadIdx.x == 0) {
        __threadfence();
        int gen = g_bar_gen;
        if (atomicAdd(&g_bar_cnt, 1) == GRID_SCAN - 1) {
            g_bar_cnt = 0;
            __threadfence();
            g_bar_gen = gen + 1;
        } else {
            while (g_bar_gen == gen) {}
        }
        __threadfence();
    }
    __syncthreads();
}

// ====== GEMM core macro: A[128,K]h (lda), W rows n0w..n0w+32 (ldw) =========
// 4-stage cp.async, issue-3-ahead, single sync per iteration.
#define PH_GEMM_CORE(Aptr, lda, K, Wptr, ldw, n0w, sA, sB)                     \
    float acc[2][2][4];                                                        \
    _Pragma("unroll")                                                          \
    for (int i = 0; i < 2; i++)                                                \
        _Pragma("unroll")                                                      \
        for (int j = 0; j < 2; j++)                                            \
            _Pragma("unroll")                                                  \
            for (int q = 0; q < 4; q++) acc[i][j][q] = 0.f;                    \
    {                                                                          \
        const int NIT = (K) >> 6;                                              \
        const int tid_ = threadIdx.x;                                          \
        const int wid_ = tid_ >> 5, lane_ = tid_ & 31;                         \
        const int wm_ = wid_ & 3, wn_ = wid_ >> 2;                             \
        auto issue = [&](int kt) {                                             \
            int st = kt & 3;                                                   \
            int k0 = kt << 6;                                                  \
            __half* pa = (sA) + st * (128 * 72);                               \
            __half* pb = (sB) + st * (32 * 72);                                \
            _Pragma("unroll")                                                  \
            for (int c = 0; c < 4; c++) {                                      \
                int idx = tid_ + 256 * c;                                      \
                int row = idx >> 3, q = (idx & 7) * 8;                         \
                cp_async16(smem_u32(pa + row * 72 + q),                        \
                           (Aptr) + (size_t)row * (lda) + k0 + q, 16);         \
            }                                                                  \
            { int row = tid_ >> 3, q = (tid_ & 7) * 8;                         \
              cp_async16(smem_u32(pb + row * 72 + q),                          \
                         (Wptr) + (size_t)((n0w) + row) * (ldw) + k0 + q, 16); } \
            CP_COMMIT();                                                       \
        };                                                                     \
        issue(0); issue(1); issue(2);                                          \
        for (int kt = 0; kt < NIT; kt++) {                                     \
            if (kt < NIT - 2)      { CP_WAIT2(); }                             \
            else if (kt == NIT - 2){ CP_WAIT1(); }                             \
            else                   { CP_WAIT0(); }                             \
            __syncthreads();                                                   \
            if (kt + 3 < NIT) issue(kt + 3);                                   \
            const __half* pa = (sA) + (kt & 3) * (128 * 72);                   \
            const __half* pb = (sB) + (kt & 3) * (32 * 72);                    \
            _Pragma("unroll")                                                  \
            for (int ks = 0; ks < 4; ks++) {                                   \
                uint32_t a_[2][4], b_[4];                                      \
                _Pragma("unroll")                                              \
                for (int i = 0; i < 2; i++)                                    \
                    ldsm_x4(a_[i], smem_u32(pa + (wm_ * 32 + i * 16 + (lane_ & 15)) * 72 \
                                               + ks * 16 + (lane_ >> 4) * 8)); \
                ldsm_x4(b_, smem_u32(pb + (wn_ * 16 + (lane_ & 7) + ((lane_ >> 4) << 3)) * 72 \
                                        + ks * 16 + ((lane_ >> 3) & 1) * 8));  \
                _Pragma("unroll")                                              \
                for (int i = 0; i < 2; i++)                                    \
                    _Pragma("unroll")                                          \
                    for (int j = 0; j < 2; j++)                                \
                        mma16816(acc[i][j], a_[i], &b_[j * 2]);                \
            }                                                                  \
        }                                                                      \
    }

// Phase A: writes C[m*ldc + n0c+..] (+bias)
__device__ void phaseA_gemm(const __half* __restrict__ A, int lda, int K,
                            const __half* __restrict__ W, int ldw, int n0w,
                            const float* __restrict__ bias,
                            float* __restrict__ C, int ldc, int n0c,
                            __half* sA, __half* sB)
{
    PH_GEMM_CORE(A, lda, K, W, ldw, n0w, sA, sB);
    const int wid = threadIdx.x >> 5, lane = threadIdx.x & 31;
    const int wm = wid & 3, wn = wid >> 2;
#pragma unroll
    for (int i = 0; i < 2; i++) {
        int m = wm * 32 + i * 16 + (lane >> 2);
#pragma unroll
        for (int j = 0; j < 2; j++) {
            int n = n0c + wn * 16 + j * 8 + (lane & 3) * 2;
            float b0 = bias ? bias[n] : 0.f;
            float b1 = bias ? bias[n + 1] : 0.f;
            C[(size_t)m * ldc + n]           = acc[i][j][0] + b0;
            C[(size_t)m * ldc + n + 1]       = acc[i][j][1] + b1;
            C[(size_t)(m + 8) * ldc + n]     = acc[i][j][2] + b0;
            C[(size_t)(m + 8) * ldc + n + 1] = acc[i][j][3] + b1;
        }
    }
}

// Phase C: adds g_gates (h-part) and writes into smem exchange sG[128][33]
__device__ void phaseC_gemm(const __half* __restrict__ A, int lda, int K,
                            const __half* __restrict__ W, int ldw, int n0w,
                            float* __restrict__ sG,
                            __half* sA, __half* sB)
{
    PH_GEMM_CORE(A, lda, K, W, ldw, n0w, sA, sB);
    const int wid = threadIdx.x >> 5, lane = threadIdx.x & 31;
    const int wm = wid & 3, wn = wid >> 2;
#pragma unroll
    for (int i = 0; i < 2; i++) {
        int m = wm * 32 + i * 16 + (lane >> 2);
#pragma unroll
        for (int j = 0; j < 2; j++) {
            int w = wn * 16 + j * 8 + (lane & 3) * 2;
            int n = n0w + w;
            sG[m * 33 + w]           = acc[i][j][0] + g_gates[(size_t)m * 2048 + n];
            sG[m * 33 + w + 1]       = acc[i][j][1] + g_gates[(size_t)m * 2048 + n + 1];
            sG[(m + 8) * 33 + w]     = acc[i][j][2] + g_gates[(size_t)(m + 8) * 2048 + n];
            sG[(m + 8) * 33 + w + 1] = acc[i][j][3] + g_gates[(size_t)(m + 8) * 2048 + n + 1];
        }
    }
}

// =================== persistent fused scan kernel ===========================
// smem: sHp 26624 | sBH 53248 | sSC 2048 | sPh 2048 |
//       sA 4*128*72*2=73728 @83968 | sB 4*32*72*2=18432 @157696 | sG @176128
#define SMEM_SCAN 193024

__global__ __launch_bounds__(256)
void scan_kernel(const float* __restrict__ batch_H,
                 const float* __restrict__ score_W,
                 const float* __restrict__ h2h_b,
                 const int* __restrict__ text)
{
    extern __shared__ char dsm[];
    __half* sHp = (__half*)dsm;
    float*  sBH = (float*)(dsm + 26624);
    float*  sSC = (float*)(dsm + 79872);
    float*  sPh = (float*)(dsm + 81920);
    __half* sA  = (__half*)(dsm + 83968);
    __half* sB  = (__half*)(dsm + 157696);
    float*  sG  = (float*)(dsm + 176128);
    __shared__ float s_e[32];

    const int b   = blockIdx.x;
    const int tid = threadIdx.x;
    const int wid = tid >> 5, lane = tid & 31;

    for (int i = tid; i < T_ * 512; i += 256) {
        sHp[i] = __float2half(g_Hproj[(size_t)b * T_ * 512 + i]);
        sBH[i] = batch_H[(size_t)b * T_ * 512 + i];
    }
#pragma unroll
    for (int i = 0; i < 2; i++) sSC[tid + 256 * i] = score_W[tid + 256 * i];
    __syncthreads();

    // LSTM cell state: CTA b<64 owns dims [8b, 8b+8) x 128 batches.
    float creg[4] = {0.f, 0.f, 0.f, 0.f};

    for (int s = 0; s < STEPS_; s++) {
        // ---- Phase A: Z = h @ [Whh_perm | h2h]^T (CTAs 0..79) ----
        if (b < 64)
            phaseA_gemm(g_xh + 512, 1024, 512, g_WA, 512, b * 32,
                        nullptr, g_gates, 2048, b * 32, sA, sB);
        else if (b < 80)
            phaseA_gemm(g_xh + 512, 1024, 512, g_WA, 512, b * 32,
                        h2h_b, g_ph, 512, b * 32 - 2048, sA, sB);
        grid_bar();

        // ---- Phase B: attention for batch b (hardware tanh) ----
#pragma unroll
        for (int i = 0; i < 2; i++)
            sPh[tid + 256 * i] = g_ph[b * 512 + tid + 256 * i];
        __syncthreads();
        for (int t = wid; t < T_; t += 8) {
            const __half* hp = sHp + t * 512;
            float sum = 0.f;
            for (int j = lane; j < 512; j += 32)
                sum += sSC[j] * tanh_fast(__half2float(hp[j]) + sPh[j]);
#pragma unroll
            for (int o = 16; o > 0; o >>= 1)
                sum += __shfl_xor_sync(0xffffffffu, sum, o);
            if (lane == 0) s_e[t] = sum;
        }
        __syncthreads();
        if (tid < 32) {
            float v = (tid < T_) ? s_e[tid] : -1e30f;
            float m = v;
#pragma unroll
            for (int o = 16; o > 0; o >>= 1)
                m = fmaxf(m, __shfl_xor_sync(0xffffffffu, m, o));
            float e = (tid < T_) ? expf(v - m) : 0.f;
            float ssum = e;
#pragma unroll
            for (int o = 16; o > 0; o >>= 1)
                ssum += __shfl_xor_sync(0xffffffffu, ssum, o);
            if (tid < T_) s_e[tid] = e / ssum;
        }
        __syncthreads();
#pragma unroll
        for (int i = 0; i < 2; i++) {
            int j = tid + 256 * i;
            float acc = 0.f;
#pragma unroll
            for (int t = 0; t < T_; t++)
                acc += s_e[t] * sBH[t * 512 + j];
            g_xh[b * 1024 + j] = __float2half(acc);
        }
        grid_bar();

        // ---- Phase C: gatesX = ctx @ Wih_perm^T + gatesH; fused LSTM ----
        if (b < 64) {
            phaseC_gemm(g_xh, 1024, 512, g_Wih_h, 512, b * 32, sG, sA, sB);
            __syncthreads();
            const int m = tid & 127, dg = tid >> 7;
            const int cls = text[m * STEPS_ + s];
            const float* wt = g_Wt + cls * 2048;
#pragma unroll
            for (int q = 0; q < 4; q++) {
                int dl = dg * 4 + q;
                int d = b * 8 + dl;
                float gi = sG[m * 33 + dl]       + wt[d];
                float gf = sG[m * 33 + 8 + dl]   + wt[512 + d];
                float gg = sG[m * 33 + 16 + dl]  + wt[1024 + d];
                float go = sG[m * 33 + 24 + dl]  + wt[1536 + d];
                float si = 1.f / (1.f + expf(-gi));
                float sf = 1.f / (1.f + expf(-gf));
                float so = 1.f / (1.f + expf(-go));
                float tg = tanhf(gg);
                float cn = sf * creg[q] + si * tg;
                creg[q] = cn;
                float hn = so * tanhf(cn);
                __half hh = __float2half(hn);
                g_xh[m * 1024 + 512 + d] = hh;
                g_Hs_h[((size_t)m * STEPS_ + s) * 512 + d] = hh;
            }
        }
        grid_bar();
    }
}

// ============ head GEMM body (R9-proven): BM=128 BN=128 BK=64, 3-stage =====
#define HD_SMEM (6 * 128 * 72 * 2)   // 110592 bytes

__device__ __forceinline__ void head_body(
    const __half* __restrict__ A, const __half* __restrict__ W,
    const float* __restrict__ bias, float* __restrict__ out,
    int Ntot, int m0, int n0, __half* sA, __half* sB)
{
    const int tid = threadIdx.x;
    const int wid = tid >> 5, lane = tid & 31;
    const int wm = wid >> 2, wn = wid & 3;     // 2 x 4 warp grid

    float acc[4][4][4];
#pragma unroll
    for (int i = 0; i < 4; i++)
#pragma unroll
        for (int j = 0; j < 4; j++)
#pragma unroll
            for (int q = 0; q < 4; q++) acc[i][j][q] = 0.f;

#define HD_ISSUE(kt) do {                                                      \
        int st = (kt) % 3;                                                     \
        int k0 = (kt) << 6;                                                    \
        __half* pa = sA + st * (128 * 72);                                     \
        __half* pb = sB + st * (128 * 72);                                     \
        _Pragma("unroll")                                                      \
        for (int c = 0; c < 4; c++) {                                          \
            int idx = tid + 256 * c;                                           \
            int row = idx >> 3, q = (idx & 7) * 8;                             \
            cp_async16(smem_u32(pa + row * 72 + q),                            \
                       A + (size_t)(m0 + row) * 512 + k0 + q, 16);             \
            cp_async16(smem_u32(pb + row * 72 + q),                            \
                       W + (size_t)(n0 + row) * 512 + k0 + q,                  \
                       (n0 + row < Ntot) ? 16 : 0);                            \
        }                                                                      \
        CP_COMMIT();                                                           \
    } while (0)

    HD_ISSUE(0);
    HD_ISSUE(1);
    for (int kt = 0; kt < 8; kt++) {
        if (kt < 7) { CP_WAIT1(); } else { CP_WAIT0(); }
        __syncthreads();
        if (kt + 2 < 8) HD_ISSUE(kt + 2);
        const __half* pa = sA + (kt % 3) * (128 * 72);
        const __half* pb = sB + (kt % 3) * (128 * 72);
#pragma unroll
        for (int ks = 0; ks < 4; ks++) {
            uint32_t a[4][4], bfr[2][4];
#pragma unroll
            for (int i = 0; i < 4; i++)
                ldsm_x4(a[i], smem_u32(pa + (wm * 64 + i * 16 + (lane & 15)) * 72
                                          + ks * 16 + (lane >> 4) * 8));
#pragma unroll
            for (int j = 0; j < 2; j++)
                ldsm_x4(bfr[j], smem_u32(pb + (wn * 32 + j * 16 + (lane & 7)
                                              + ((lane >> 4) << 3)) * 72
                                            + ks * 16 + ((lane >> 3) & 1) * 8));
#pragma unroll
            for (int i = 0; i < 4; i++)
#pragma unroll
                for (int j = 0; j < 4; j++)
                    mma16816(acc[i][j], a[i], &bfr[j >> 1][(j & 1) * 2]);
        }
    }
#undef HD_ISSUE

#pragma unroll
    for (int i = 0; i < 4; i++) {
        int mBase = m0 + wm * 64 + i * 16 + (lane >> 2);
#pragma unroll
        for (int j = 0; j < 4; j++) {
            int n = n0 + wn * 32 + j * 8 + (lane & 3) * 2;
            if (n < Ntot) {
                float b0 = bias[n];
                float b1 = (n + 1 < Ntot) ? bias[n + 1] : 0.f;
                float* p0 = out + (size_t)mBase * Ntot + n;
                float* p1 = out + (size_t)(mBase + 8) * Ntot + n;
                p0[0] = acc[i][j][0] + b0;
                p1[0] = acc[i][j][2] + b0;
                if (n + 1 < Ntot) {
                    p0[1] = acc[i][j][1] + b1;
                    p1[1] = acc[i][j][3] + b1;
                }
            }
        }
    }
}

__global__ __launch_bounds__(256, 2)
void head_gemm_mma(const __half* __restrict__ A, const __half* __restrict__ W,
                   const float* __restrict__ bias, float* __restrict__ out,
                   int Ntot)
{
    extern __shared__ __half hsm[];
    head_body(A, W, bias, out, Ntot, blockIdx.x * 128, blockIdx.y * 128,
              hsm, hsm + 3 * 128 * 72);
}

__global__ __launch_bounds__(256, 2)
void head_gemm_multi(const __half* __restrict__ A,
                     const __half* W0, const float* b0, float* o0, int N0,
                     const __half* W1, const float* b1, float* o1, int N1,
                     const __half* W2, const float* b2, float* o2, int N2,
                     int y1, int y2)
{
    extern __shared__ __half hsm[];
    const int y = blockIdx.y;
    const __half* W; const float* bias; float* out; int Ntot, n0;
    if (y < y1)      { W = W0; bias = b0; out = o0; Ntot = N0; n0 = y * 128; }
    else if (y < y2) { W = W1; bias = b1; out = o1; Ntot = N1; n0 = (y - y1) * 128; }
    else             { W = W2; bias = b2; out = o2; Ntot = N2; n0 = (y - y2) * 128; }
    head_body(A, W, bias, out, Ntot, blockIdx.x * 128, n0,
              hsm, hsm + 3 * 128 * 72);
}

// ---------------- fused prep kernel (segments by blockIdx.x) ---------------
// [0,512): zero g_xh | [512,5632): build WA | [5632,9728): build Wih_h |
// [9728,9766): build Wt | [9766,10022): i2h->fp16 | [10022,11686): batch_H->fp16
__global__ void prep_kernel(const float* __restrict__ h2h_W,
                            const float* __restrict__ Wih,
                            const float* __restrict__ Whh,
                            const float* __restrict__ bih,
                            const float* __restrict__ bhh,
                            const float* __restrict__ i2h_W,
                            const float* __restrict__ batch_H)
{
    const int blk = blockIdx.x, tid = threadIdx.x;
    if (blk < 512) {
        g_xh[blk * 256 + tid] = __float2half(0.f);
    } else if (blk < 5632) {
        int i = (blk - 512) * 256 + tid;               // 2560*512 elems
        int r = i >> 9, k = i & 511;
        float v;
        if (r < 2048) {
            int grp = r >> 5, w = r & 31;
            int orig = ((w >> 3) << 9) + (grp << 3) + (w & 7);
            v = Whh[(size_t)orig * 512 + k];
        } else {
            v = h2h_W[(size_t)(r - 2048) * 512 + k];
        }
        g_WA[(size_t)r * 512 + k] = __float2half(v);
    } else if (blk < 9728) {
        int i = (blk - 5632) * 256 + tid;              // 2048*512 elems
        int r = i >> 9, k = i & 511;
        int grp = r >> 5, w = r & 31;
        int orig = ((w >> 3) << 9) + (grp << 3) + (w & 7);
        g_Wih_h[(size_t)r * 512 + k] = __float2half(Wih[(size_t)orig * 550 + k]);
    } else if (blk < 9766) {
        int c = blk - 9728;
        for (int n = tid; n < 2048; n += 256)
            g_Wt[c * 2048 + n] = Wih[(size_t)n * 550 + 512 + c] + bih[n] + bhh[n];
    } else if (blk < 10022) {
        int i = (blk - 9766) * 256 + tid;              // n4 = 65536
        float4 v = ((const float4*)i2h_W)[i];
        ((__half2*)g_i2h_h)[2 * i]     = __floats2half2_rn(v.x, v.y);
        ((__half2*)g_i2h_h)[2 * i + 1] = __floats2half2_rn(v.z, v.w);
    } else {
        int i = (blk - 10022) * 256 + tid;             // n4 = 425984
        if (i < 425984) {
            float4 v = ((const float4*)batch_H)[i];
            ((__half2*)g_bh_h)[2 * i]     = __floats2half2_rn(v.x, v.y);
            ((__half2*)g_bh_h)[2 * i + 1] = __floats2half2_rn(v.z, v.w);
        }
    }
}

__global__ void cvt_half(const float* __restrict__ src, __half* __restrict__ dst, int n4) {
    int i = blockIdx.x * blockDim.x + threadIdx.x;
    if (i < n4) {
        float4 v = ((const float4*)src)[i];
        ((__half2*)dst)[2 * i]     = __floats2half2_rn(v.x, v.y);
        ((__half2*)dst)[2 * i + 1] = __floats2half2_rn(v.z, v.w);
    }
}

// ---------------- launcher ----------------
extern "C" void kernel_launch(void* const* d_in, const int* in_sizes, int n_in,
                              void* d_out, int out_size)
{
    const float* batch_H = (const float*)d_in[0];
    const int*   text    = (const int*)  d_in[1];
    const float* i2h_W   = (const float*)d_in[2];
    const float* h2h_W   = (const float*)d_in[3];
    const float* h2h_b   = (const float*)d_in[4];
    const float* score_W = (const float*)d_in[5];
    const float* rnn_Wih = (const float*)d_in[6];
    const float* rnn_bih = (const float*)d_in[7];
    const float* rnn_Whh = (const float*)d_in[8];
    const float* rnn_bhh = (const float*)d_in[9];
    const float* char_W  = (const float*)d_in[10];
    const float* char_b  = (const float*)d_in[11];
    const float* bpe_W   = (const float*)d_in[12];
    const float* bpe_b   = (const float*)d_in[13];
    const float* wp_W    = (const float*)d_in[14];
    const float* wp_b    = (const float*)d_in[15];
    float* out = (float*)d_out;

    float *d_Hproj, *d_zeros;
    __half *d_Hs_h, *d_char_h, *d_bpe_h, *d_wp_h, *d_i2h_h, *d_bh_h;
    cudaGetSymbolAddress((void**)&d_Hproj,  g_Hproj);
    cudaGetSymbolAddress((void**)&d_Hs_h,   g_Hs_h);
    cudaGetSymbolAddress((void**)&d_char_h, g_char_h);
    cudaGetSymbolAddress((void**)&d_bpe_h,  g_bpe_h);
    cudaGetSymbolAddress((void**)&d_wp_h,   g_wp_h);
    cudaGetSymbolAddress((void**)&d_i2h_h,  g_i2h_h);
    cudaGetSymbolAddress((void**)&d_bh_h,   g_bh_h);
    cudaGetSymbolAddress((void**)&d_zeros,  g_zeros);

    cudaFuncSetAttribute(scan_kernel,
                         cudaFuncAttributeMaxDynamicSharedMemorySize, SMEM_SCAN);
    cudaFuncSetAttribute(head_gemm_mma,
                         cudaFuncAttributeMaxDynamicSharedMemorySize, HD_SMEM);
    cudaFuncSetAttribute(head_gemm_multi,
                         cudaFuncAttributeMaxDynamicSharedMemorySize, HD_SMEM);

    // 1) fused prep
    prep_kernel<<<11686, 256>>>(h2h_W, rnn_Wih, rnn_Whh, rnn_bih, rnn_bhh,
                                i2h_W, batch_H);
    // 2) Hproj = batch_H @ i2h^T via fp16 mma (zero bias)
    head_gemm_mma<<<dim3(26, 4), 256, HD_SMEM>>>(d_bh_h, d_i2h_h, d_zeros,
                                                 d_Hproj, 512);
    // 3) bpe weights -> fp16 (keeps scan as 4th launch for ncu)
    cvt_half<<<(BPE_ * H_ / 4 + 255) / 256, 256>>>(bpe_W, d_bpe_h, BPE_ * H_ / 4);
    // 4) fused persistent scan (profiled launch)
    scan_kernel<<<GRID_SCAN, 256, SMEM_SCAN>>>(batch_H, score_W, h2h_b, text);
    // 5-6) remaining weight conversions
    cvt_half<<<(NC_ * H_ / 4 + 255) / 256, 256>>>(char_W, d_char_h, NC_ * H_ / 4);
    cvt_half<<<(WP_ * H_ / 4 + 255) / 256, 256>>>(wp_W, d_wp_h, WP_ * H_ / 4);

    // 7) all three heads in one launch: [bpe | wp | char]
    const long long off_bpe = (long long)ROWS_ * NC_;
    const long long off_wp  = off_bpe + (long long)ROWS_ * BPE_;
    const int y_bpe = (BPE_ + 127) / 128;          // 393
    const int y_wp  = (WP_ + 127) / 128;           // 239
    head_gemm_multi<<<dim3(26, y_bpe + y_wp + 1), 256, HD_SMEM>>>(
        d_Hs_h,
        d_bpe_h,  bpe_b,  out + off_bpe, BPE_,
        d_wp_h,   wp_b,   out + off_wp,  WP_,
        d_char_h, char_b, out,           NC_,
        y_bpe, y_bpe + y_wp);
}